// round 12
// baseline (speedup 1.0000x reference)
#include <cuda_runtime.h>
#include <cuda_bf16.h>
#include <mma.h>
#include <math.h>
#include <stdint.h>

using namespace nvcuda;

#define NB 64
#define TT 1024
#define DD 1024
#define HH 1024
#define K4 4096
#define NCTA_REC 128
#define GP 68          // smem pitch for fp32 staging (elements)

// ---------------- device globals ----------------
__device__ float g_xW[(size_t)TT * K4 * NB];          // [t][k'][n]
__device__ __nv_bfloat16 g_WhT_hi[(size_t)K4 * HH];   // [k'][j]
__device__ __nv_bfloat16 g_WhT_lo[(size_t)K4 * HH];
__device__ __nv_bfloat16 g_WxT_hi[(size_t)K4 * DD];   // [k'][d]
__device__ __nv_bfloat16 g_WxT_lo[(size_t)K4 * DD];
__device__ __nv_bfloat16 g_xh[(size_t)NB * TT * DD];  // [n][t][d]
__device__ __nv_bfloat16 g_xl[(size_t)NB * TT * DD];
__device__ __nv_bfloat16 g_hh[2][(size_t)NB * HH];    // [buf][n][j]
__device__ __nv_bfloat16 g_hl[2][(size_t)NB * HH];
__device__ unsigned int g_bar_count;
__device__ unsigned int g_bar_gen;

__device__ __forceinline__ float sigf(float v) { return 1.0f / (1.0f + __expf(-v)); }
__device__ __forceinline__ float tanhf_fast(float v) {
    float x = fminf(fmaxf(v, -15.0f), 15.0f);
    float e = __expf(2.0f * x);
    return (e - 1.0f) / (e + 1.0f);
}

// ---------------------------------------------------------------------------
// Preps (unchanged, validated)
// ---------------------------------------------------------------------------
__global__ void xsplit_kernel(const float* __restrict__ x) {
    size_t i = (size_t)blockIdx.x * 256 + threadIdx.x;   // 64M
    float v = x[i];
    __nv_bfloat16 h = __float2bfloat16(v);
    g_xh[i] = h;
    g_xl[i] = __float2bfloat16(v - __bfloat162float(h));
}

__global__ void wprep_kernel(const float* __restrict__ W, int which) {
    __nv_bfloat16* __restrict__ dhi = which ? g_WhT_hi : g_WxT_hi;
    __nv_bfloat16* __restrict__ dlo = which ? g_WhT_lo : g_WxT_lo;
    const int k0 = blockIdx.x * 32;
    const int j0 = blockIdx.y * 32;
    __shared__ float tile[32][33];
    const int tid = threadIdx.x;
    const int jj = tid >> 5, kk = tid & 31;
    #pragma unroll
    for (int p = 0; p < 4; p++)
        tile[jj + 8 * p][kk] = W[(size_t)(j0 + jj + 8 * p) * K4 + k0 + kk];
    __syncthreads();
    const int r = tid >> 3, j4 = (tid & 7) * 4;
    const int korig = k0 + r;
    const int gate = korig >> 10, jout = korig & 1023;
    const int kp = (jout >> 3) * 32 + gate * 8 + (jout & 7);
    __nv_bfloat16 hi4[4], lo4[4];
    #pragma unroll
    for (int u = 0; u < 4; u++) {
        float v = tile[j4 + u][r];
        __nv_bfloat16 h = __float2bfloat16(v);
        hi4[u] = h;
        lo4[u] = __float2bfloat16(v - __bfloat162float(h));
    }
    size_t o = (size_t)kp * HH + j0 + j4;
    *(uint2*)&dhi[o] = *(uint2*)hi4;
    *(uint2*)&dlo[o] = *(uint2*)lo4;
}

__global__ void init_kernel(const float* __restrict__ h0) {
    int i = blockIdx.x * 256 + threadIdx.x;   // 65536, [n][j]
    float v = h0[i];
    __nv_bfloat16 h = __float2bfloat16(v);
    g_hh[0][i] = h;
    g_hl[0][i] = __float2bfloat16(v - __bfloat162float(h));
    if (i == 0) { g_bar_count = 0; g_bar_gen = 0; }
}

// ---------------------------------------------------------------------------
// GEMM core: fragments load DIRECTLY FROM GLOBAL (no smem staging, no
// mainloop syncthreads). CTA tile 32 k'-rows (m) x 64 n; 8 warps = 4 (ks
// quarter q) x 2 (n-half p); warp tile 32x32 at its q. Two fragment sets
// give a one-chunk-ahead register pipeline hiding L2 latency.
// Partial sums over q reduced via per-lane fragment blobs in smem.
// ---------------------------------------------------------------------------
#define ACCX(j) acc[(j) >> 4][((j) >> 3) & 1].x[(j) & 7]

#define DECL_FRAGSET(S) \
    wmma::fragment<wmma::matrix_a, 16, 16, 16, __nv_bfloat16, wmma::row_major> fah##S[2], fal##S[2]; \
    wmma::fragment<wmma::matrix_b, 16, 16, 16, __nv_bfloat16, wmma::col_major> fbh##S[2], fbl##S[2];

// pAh/pAl: A base incl. q-offset (element [m=0][k=q*16]), row stride LDA_
// pBh/pBl: B base incl. q- and p-offset (element [n=p*32][k=q*16]), row stride LDB_
#define LOAD_FRAGSET(S, koff_)                                                   \
    do {                                                                         \
        _Pragma("unroll")                                                        \
        for (int mi = 0; mi < 2; mi++) {                                         \
            wmma::load_matrix_sync(fah##S[mi], pAh + (size_t)(mi * 16) * LDA_ + (koff_), LDA_); \
            wmma::load_matrix_sync(fal##S[mi], pAl + (size_t)(mi * 16) * LDA_ + (koff_), LDA_); \
        }                                                                        \
        _Pragma("unroll")                                                        \
        for (int ni = 0; ni < 2; ni++) {                                         \
            wmma::load_matrix_sync(fbh##S[ni], pBh + (size_t)(ni * 16) * LDB_ + (koff_), LDB_); \
            wmma::load_matrix_sync(fbl##S[ni], pBl + (size_t)(ni * 16) * LDB_ + (koff_), LDB_); \
        }                                                                        \
    } while (0)

#define MMA_FRAGSET(S)                                                           \
    do {                                                                         \
        _Pragma("unroll")                                                        \
        for (int mi = 0; mi < 2; mi++)                                           \
            _Pragma("unroll")                                                    \
            for (int ni = 0; ni < 2; ni++) {                                     \
                wmma::mma_sync(acc[mi][ni], fah##S[mi], fbh##S[ni], acc[mi][ni]); \
                wmma::mma_sync(acc[mi][ni], fal##S[mi], fbh##S[ni], acc[mi][ni]); \
                wmma::mma_sync(acc[mi][ni], fah##S[mi], fbl##S[ni], acc[mi][ni]); \
            }                                                                    \
    } while (0)

#define STORE_BLOB(rsm_, slot_)                                                  \
    do {                                                                         \
        float* bp_ = (rsm_) + (slot_) * 1024 + lane * 4;                         \
        _Pragma("unroll")                                                        \
        for (int e4 = 0; e4 < 8; e4++) {                                         \
            int j_ = e4 * 4;                                                     \
            *(float4*)(bp_ + e4 * 128) =                                         \
                make_float4(ACCX(j_), ACCX(j_ + 1), ACCX(j_ + 2), ACCX(j_ + 3)); \
        }                                                                        \
    } while (0)

#define LOAD_BLOB_ADD(rsm_, slot_)                                               \
    do {                                                                         \
        const float* bp_ = (rsm_) + (slot_) * 1024 + lane * 4;                   \
        _Pragma("unroll")                                                        \
        for (int e4 = 0; e4 < 8; e4++) {                                         \
            int j_ = e4 * 4;                                                     \
            float4 v_ = *(const float4*)(bp_ + e4 * 128);                        \
            ACCX(j_) += v_.x; ACCX(j_ + 1) += v_.y;                              \
            ACCX(j_ + 2) += v_.z; ACCX(j_ + 3) += v_.w;                          \
        }                                                                        \
    } while (0)

#define REDUCE_Q(rsm_)                                                           \
    do {                                                                         \
        __syncthreads();                                                         \
        if (q >= 2) STORE_BLOB(rsm_, (q - 2) * 2 + p);                           \
        __syncthreads();                                                         \
        if (q < 2) LOAD_BLOB_ADD(rsm_, q * 2 + p);                               \
        __syncthreads();                                                         \
        if (q == 1) STORE_BLOB(rsm_, p);                                         \
        __syncthreads();                                                         \
        if (q == 0) LOAD_BLOB_ADD(rsm_, p);                                      \
    } while (0)

#define MAINLOOP_16()                                                            \
    do {                                                                         \
        LOAD_FRAGSET(0, 0);                                                      \
        _Pragma("unroll")                                                        \
        for (int c = 0; c < 16; c += 2) {                                        \
            if (c + 1 < 16) LOAD_FRAGSET(1, (size_t)(c + 1) * 64);               \
            MMA_FRAGSET(0);                                                      \
            if (c + 2 < 16) LOAD_FRAGSET(0, (size_t)(c + 2) * 64);               \
            MMA_FRAGSET(1);                                                      \
        }                                                                        \
    } while (0)

// ---------------------------------------------------------------------------
// Phase 1: g_xW[t][k'][n] = x @ Wx + b
// ---------------------------------------------------------------------------
__global__ __launch_bounds__(256) void phase1_wmma(const float* __restrict__ b) {
    __shared__ float rsm[4 * 1024];
    __shared__ float ssm[32 * GP];
    const int tid = threadIdx.x;
    const int w = tid >> 5, lane = tid & 31;
    const int q = w >> 1, p = w & 1;
    const int cta = blockIdx.x;       // k' block (0..127)
    const int t = blockIdx.y;

    const unsigned LDA_ = DD;
    const unsigned LDB_ = TT * DD;
    const __nv_bfloat16* pAh = g_WxT_hi + (size_t)(cta * 32) * DD + q * 16;
    const __nv_bfloat16* pAl = g_WxT_lo + (size_t)(cta * 32) * DD + q * 16;
    const __nv_bfloat16* pBh = g_xh + (size_t)(p * 32) * TT * DD + (size_t)t * DD + q * 16;
    const __nv_bfloat16* pBl = g_xl + (size_t)(p * 32) * TT * DD + (size_t)t * DD + q * 16;

    wmma::fragment<wmma::accumulator, 16, 16, 16, float> acc[2][2];
    #pragma unroll
    for (int mi = 0; mi < 2; mi++)
        #pragma unroll
        for (int ni = 0; ni < 2; ni++) wmma::fill_fragment(acc[mi][ni], 0.0f);

    DECL_FRAGSET(0)
    DECL_FRAGSET(1)
    MAINLOOP_16();

    REDUCE_Q(rsm);
    __syncthreads();
    if (q == 0) {
        #pragma unroll
        for (int mi = 0; mi < 2; mi++)
            #pragma unroll
            for (int ni = 0; ni < 2; ni++)
                wmma::store_matrix_sync(ssm + (mi * 16) * GP + p * 32 + ni * 16,
                                        acc[mi][ni], GP, wmma::mem_row_major);
    }
    __syncthreads();

    float* xwo = g_xW + ((size_t)t * K4 + cta * 32) * 64;
    #pragma unroll
    for (int u = 0; u < 8; u++) {
        const int idx = tid + 256 * u;
        const int lm = idx >> 6, n = idx & 63;
        const int korig = (lm >> 3) * 1024 + cta * 8 + (lm & 7);
        xwo[idx] = ssm[lm * GP + n] + __ldg(&b[korig]);
    }
}

// ---------------------------------------------------------------------------
// Persistent recurrence. 128 CTAs, grid barrier per step. No mainloop syncs.
// ---------------------------------------------------------------------------
__global__ __launch_bounds__(256, 1) void rec_wmma(float* __restrict__ out) {
    __shared__ float rsm[4 * 1024];
    __shared__ float gsm[32 * GP];
    __shared__ float csm[8 * GP];
    const int tid = threadIdx.x;
    const int w = tid >> 5, lane = tid & 31;
    const int q = w >> 1, p = w & 1;
    const int cta = blockIdx.x;

    const unsigned LDA_ = HH;
    const unsigned LDB_ = HH;
    const __nv_bfloat16* pAh = g_WhT_hi + (size_t)(cta * 32) * HH + q * 16;
    const __nv_bfloat16* pAl = g_WhT_lo + (size_t)(cta * 32) * HH + q * 16;

    for (int i = tid; i < 8 * GP; i += 256) csm[i] = 0.f;
    __syncthreads();

    const int cn = tid >> 2;            // n for combine
    const int jp = (tid & 3) * 2;       // jl pair base

    for (int t = 0; t < TT; t++) {
        const __nv_bfloat16* pBh = g_hh[t & 1] + (size_t)(p * 32) * HH + q * 16;
        const __nv_bfloat16* pBl = g_hl[t & 1] + (size_t)(p * 32) * HH + q * 16;

        const float* xwp = g_xW + ((size_t)t * K4 + cta * 32) * 64;
        float xwr[8];
        #pragma unroll
        for (int u = 0; u < 8; u++) xwr[u] = __ldg(&xwp[tid + 256 * u]);

        wmma::fragment<wmma::accumulator, 16, 16, 16, float> acc[2][2];
        #pragma unroll
        for (int mi = 0; mi < 2; mi++)
            #pragma unroll
            for (int ni = 0; ni < 2; ni++) wmma::fill_fragment(acc[mi][ni], 0.0f);

        DECL_FRAGSET(0)
        DECL_FRAGSET(1)
        MAINLOOP_16();

        REDUCE_Q(rsm);
        __syncthreads();
        if (q == 0) {
            #pragma unroll
            for (int mi = 0; mi < 2; mi++)
                #pragma unroll
                for (int ni = 0; ni < 2; ni++)
                    wmma::store_matrix_sync(gsm + (mi * 16) * GP + p * 32 + ni * 16,
                                            acc[mi][ni], GP, wmma::mem_row_major);
        }
        __syncthreads();

        // activation: lm = gate*8 + jl; gate 3 (lm>=24) uses tanh
        #pragma unroll
        for (int u = 0; u < 8; u++) {
            const int idx = tid + 256 * u;
            const int lm = idx >> 6, n = idx & 63;
            const float v = gsm[lm * GP + n] + xwr[u];
            gsm[lm * GP + n] = (lm >= 24) ? tanhf_fast(v) : sigf(v);
        }
        __syncthreads();

        // combine
        float hv[2];
        __nv_bfloat16 hh2[2], hl2[2];
        #pragma unroll
        for (int u = 0; u < 2; u++) {
            const int jl = jp + u;
            const float iv = gsm[(jl)      * GP + cn];
            const float fv = gsm[(8 + jl)  * GP + cn];
            const float ov = gsm[(16 + jl) * GP + cn];
            const float gv = gsm[(24 + jl) * GP + cn];
            const float cprev = csm[jl * GP + cn];
            const float cnew = fv * cprev + iv * gv;
            csm[jl * GP + cn] = cnew;
            const float h = ov * tanhf_fast(cnew);
            hv[u] = h;
            const __nv_bfloat16 hb = __float2bfloat16(h);
            hh2[u] = hb;
            hl2[u] = __float2bfloat16(h - __bfloat162float(hb));
        }
        *(float2*)&out[((size_t)cn * TT + t) * HH + cta * 8 + jp] = make_float2(hv[0], hv[1]);
        const int nb = (t + 1) & 1;
        *(uint32_t*)&g_hh[nb][(size_t)cn * HH + cta * 8 + jp] = *(uint32_t*)hh2;
        *(uint32_t*)&g_hl[nb][(size_t)cn * HH + cta * 8 + jp] = *(uint32_t*)hl2;

        // grid barrier
        __syncthreads();
        if (tid == 0) {
            __threadfence();
            unsigned int ticket = atomicAdd(&g_bar_count, 1);
            if (ticket == NCTA_REC - 1) {
                g_bar_count = 0;
                __threadfence();
                atomicAdd(&g_bar_gen, 1);
            } else {
                while (*(volatile unsigned int*)&g_bar_gen < (unsigned)(t + 1)) { }
            }
            __threadfence();
        }
        __syncthreads();
    }
}

// ---------------------------------------------------------------------------
extern "C" void kernel_launch(void* const* d_in, const int* in_sizes, int n_in,
                              void* d_out, int out_size)
{
    (void)in_sizes; (void)n_in; (void)out_size;
    const float* x  = (const float*)d_in[0];
    const float* h0 = (const float*)d_in[1];
    const float* Wx = (const float*)d_in[2];
    const float* Wh = (const float*)d_in[3];
    const float* b  = (const float*)d_in[4];
    float* out = (float*)d_out;

    xsplit_kernel<<<262144, 256>>>(x);
    wprep_kernel<<<dim3(128, 32), 256>>>(Wx, 0);   // -> g_WxT_hi/lo
    wprep_kernel<<<dim3(128, 32), 256>>>(Wh, 1);   // -> g_WhT_hi/lo
    init_kernel<<<256, 256>>>(h0);
    phase1_wmma<<<dim3(128, 1024), 256>>>(b);
    rec_wmma<<<NCTA_REC, 256>>>(out);
}

// round 13
// speedup vs baseline: 1.6099x; 1.6099x over previous
#include <cuda_runtime.h>
#include <cuda_bf16.h>
#include <mma.h>
#include <math.h>
#include <stdint.h>

using namespace nvcuda;

#define NB 64
#define TT 1024
#define DD 1024
#define HH 1024
#define K4 4096
#define NCTA_REC 128
#define PE 72                       // bf16 smem pitch (144B rows, odd 16B multiple)
#define GP 68                       // fp32 staging pitch
#define STAGE_E (192 * PE)          // elements per stage (A hi/lo 32 rows + B hi/lo 64 rows)
#define STAGE_B (STAGE_E * 2)       // 27648 bytes
#define DYN_B   (2 * STAGE_B)       // 55296 bytes
#define OAL_B  (32 * PE * 2)
#define OBH_B  (64 * PE * 2)
#define OBL_B  (128 * PE * 2)

// ---------------- device globals ----------------
__device__ float g_xW[(size_t)TT * K4 * NB];          // [t][k'][n]
__device__ __nv_bfloat16 g_WhT_hi[(size_t)K4 * HH];   // [k'][j]
__device__ __nv_bfloat16 g_WhT_lo[(size_t)K4 * HH];
__device__ __nv_bfloat16 g_WxT_hi[(size_t)K4 * DD];   // [k'][d]
__device__ __nv_bfloat16 g_WxT_lo[(size_t)K4 * DD];
__device__ __nv_bfloat16 g_xh[(size_t)NB * TT * DD];  // [n][t][d]
__device__ __nv_bfloat16 g_xl[(size_t)NB * TT * DD];
__device__ __nv_bfloat16 g_hh[2][(size_t)NB * HH];    // [buf][n][j]
__device__ __nv_bfloat16 g_hl[2][(size_t)NB * HH];
__device__ unsigned int g_bar_count;
__device__ unsigned int g_bar_gen;

__device__ __forceinline__ float sigf(float v) { return 1.0f / (1.0f + __expf(-v)); }
__device__ __forceinline__ float tanhf_fast(float v) {
    float x = fminf(fmaxf(v, -15.0f), 15.0f);
    float e = __expf(2.0f * x);
    return (e - 1.0f) / (e + 1.0f);
}
__device__ __forceinline__ uint32_t smem_u32(const void* p) {
    uint32_t a;
    asm("{ .reg .u64 t; cvta.to.shared.u64 t, %1; cvt.u32.u64 %0, t; }"
        : "=r"(a) : "l"(p));
    return a;
}
__device__ __forceinline__ void cp16(uint32_t dst, const void* src) {
    asm volatile("cp.async.cg.shared.global [%0], [%1], 16;" :: "r"(dst), "l"(src));
}
#define CP_COMMIT() asm volatile("cp.async.commit_group;" ::: "memory")
#define CP_WAIT0()  asm volatile("cp.async.wait_group 0;" ::: "memory")

// ---------------------------------------------------------------------------
// Preps (unchanged, validated)
// ---------------------------------------------------------------------------
__global__ void xsplit_kernel(const float* __restrict__ x) {
    size_t i = (size_t)blockIdx.x * 256 + threadIdx.x;   // 64M
    float v = x[i];
    __nv_bfloat16 h = __float2bfloat16(v);
    g_xh[i] = h;
    g_xl[i] = __float2bfloat16(v - __bfloat162float(h));
}

__global__ void wprep_kernel(const float* __restrict__ W, int which) {
    __nv_bfloat16* __restrict__ dhi = which ? g_WhT_hi : g_WxT_hi;
    __nv_bfloat16* __restrict__ dlo = which ? g_WhT_lo : g_WxT_lo;
    const int k0 = blockIdx.x * 32;
    const int j0 = blockIdx.y * 32;
    __shared__ float tile[32][33];
    const int tid = threadIdx.x;
    const int jj = tid >> 5, kk = tid & 31;
    #pragma unroll
    for (int p = 0; p < 4; p++)
        tile[jj + 8 * p][kk] = W[(size_t)(j0 + jj + 8 * p) * K4 + k0 + kk];
    __syncthreads();
    const int r = tid >> 3, j4 = (tid & 7) * 4;
    const int korig = k0 + r;
    const int gate = korig >> 10, jout = korig & 1023;
    const int kp = (jout >> 3) * 32 + gate * 8 + (jout & 7);
    __nv_bfloat16 hi4[4], lo4[4];
    #pragma unroll
    for (int u = 0; u < 4; u++) {
        float v = tile[j4 + u][r];
        __nv_bfloat16 h = __float2bfloat16(v);
        hi4[u] = h;
        lo4[u] = __float2bfloat16(v - __bfloat162float(h));
    }
    size_t o = (size_t)kp * HH + j0 + j4;
    *(uint2*)&dhi[o] = *(uint2*)hi4;
    *(uint2*)&dlo[o] = *(uint2*)lo4;
}

__global__ void init_kernel(const float* __restrict__ h0) {
    int i = blockIdx.x * 256 + threadIdx.x;   // 65536, [n][j]
    float v = h0[i];
    __nv_bfloat16 h = __float2bfloat16(v);
    g_hh[0][i] = h;
    g_hl[0][i] = __float2bfloat16(v - __bfloat162float(h));
    if (i == 0) { g_bar_count = 0; g_bar_gen = 0; }
}

// ---------------------------------------------------------------------------
// GEMM core (R11 layout, cp.async double-buffered). CTA tile 32 k' x 64 n.
// 8 warps = 4 (ks quarter q) x 2 (n-half p), warp tile 32x32 at its q.
// One __syncthreads per chunk; load of chunk c+1 overlaps compute of c.
// ---------------------------------------------------------------------------
#define ACCX(j) acc[(j) >> 4][((j) >> 3) & 1].x[(j) & 7]

// issue all 6 cp16 for one chunk into stage at byte offset stOff_
#define ISSUE_CHUNK(stOff_, co_)                                                 \
    do {                                                                         \
        cp16(sb + (stOff_) + dA,          srcAh + (co_));                        \
        cp16(sb + (stOff_) + OAL_B + dA,  srcAl + (co_));                        \
        cp16(sb + (stOff_) + OBH_B + dB0, srcBh0 + (co_));                       \
        cp16(sb + (stOff_) + OBH_B + dB1, srcBh1 + (co_));                       \
        cp16(sb + (stOff_) + OBL_B + dB0, srcBl0 + (co_));                       \
        cp16(sb + (stOff_) + OBL_B + dB1, srcBl1 + (co_));                       \
        CP_COMMIT();                                                             \
    } while (0)

#define WMMA_CHUNK(stage_)                                                       \
    do {                                                                         \
        const __nv_bfloat16* sAh_ = (stage_);                                    \
        const __nv_bfloat16* sAl_ = (stage_) + 32 * PE;                          \
        const __nv_bfloat16* sBh_ = (stage_) + 64 * PE;                          \
        const __nv_bfloat16* sBl_ = (stage_) + 128 * PE;                         \
        wmma::fragment<wmma::matrix_a, 16, 16, 16, __nv_bfloat16, wmma::row_major> fah[2], fal[2]; \
        wmma::fragment<wmma::matrix_b, 16, 16, 16, __nv_bfloat16, wmma::col_major> fbh[2], fbl[2]; \
        _Pragma("unroll")                                                        \
        for (int mi = 0; mi < 2; mi++) {                                         \
            wmma::load_matrix_sync(fah[mi], sAh_ + (mi * 16) * PE + q * 16, PE); \
            wmma::load_matrix_sync(fal[mi], sAl_ + (mi * 16) * PE + q * 16, PE); \
        }                                                                        \
        _Pragma("unroll")                                                        \
        for (int ni = 0; ni < 2; ni++) {                                         \
            wmma::load_matrix_sync(fbh[ni], sBh_ + (p * 32 + ni * 16) * PE + q * 16, PE); \
            wmma::load_matrix_sync(fbl[ni], sBl_ + (p * 32 + ni * 16) * PE + q * 16, PE); \
        }                                                                        \
        _Pragma("unroll")                                                        \
        for (int mi = 0; mi < 2; mi++)                                           \
            _Pragma("unroll")                                                    \
            for (int ni = 0; ni < 2; ni++) {                                     \
                wmma::mma_sync(acc[mi][ni], fah[mi], fbh[ni], acc[mi][ni]);      \
                wmma::mma_sync(acc[mi][ni], fal[mi], fbh[ni], acc[mi][ni]);      \
                wmma::mma_sync(acc[mi][ni], fah[mi], fbl[ni], acc[mi][ni]);      \
            }                                                                    \
    } while (0)

#define MAINLOOP_16()                                                            \
    do {                                                                         \
        ISSUE_CHUNK(0, 0);                                                       \
        _Pragma("unroll")                                                        \
        for (int c = 0; c < 16; c++) {                                           \
            CP_WAIT0();                                                          \
            __syncthreads();                                                     \
            if (c < 15) ISSUE_CHUNK(((c + 1) & 1) * STAGE_B, (size_t)(c + 1) * 128); \
            WMMA_CHUNK((__nv_bfloat16*)(dsm + (c & 1) * STAGE_B));               \
        }                                                                        \
    } while (0)

#define STORE_BLOB(rsm_, slot_)                                                  \
    do {                                                                         \
        float* bp_ = (rsm_) + (slot_) * 1024 + lane * 4;                         \
        _Pragma("unroll")                                                        \
        for (int e4 = 0; e4 < 8; e4++) {                                         \
            int j_ = e4 * 4;                                                     \
            *(float4*)(bp_ + e4 * 128) =                                         \
                make_float4(ACCX(j_), ACCX(j_ + 1), ACCX(j_ + 2), ACCX(j_ + 3)); \
        }                                                                        \
    } while (0)

#define LOAD_BLOB_ADD(rsm_, slot_)                                               \
    do {                                                                         \
        const float* bp_ = (rsm_) + (slot_) * 1024 + lane * 4;                   \
        _Pragma("unroll")                                                        \
        for (int e4 = 0; e4 < 8; e4++) {                                         \
            int j_ = e4 * 4;                                                     \
            float4 v_ = *(const float4*)(bp_ + e4 * 128);                        \
            ACCX(j_) += v_.x; ACCX(j_ + 1) += v_.y;                              \
            ACCX(j_ + 2) += v_.z; ACCX(j_ + 3) += v_.w;                          \
        }                                                                        \
    } while (0)

#define REDUCE_Q(rsm_)                                                           \
    do {                                                                         \
        __syncthreads();                                                         \
        if (q >= 2) STORE_BLOB(rsm_, (q - 2) * 2 + p);                           \
        __syncthreads();                                                         \
        if (q < 2) LOAD_BLOB_ADD(rsm_, q * 2 + p);                               \
        __syncthreads();                                                         \
        if (q == 1) STORE_BLOB(rsm_, p);                                         \
        __syncthreads();                                                         \
        if (q == 0) LOAD_BLOB_ADD(rsm_, p);                                      \
    } while (0)

// ---------------------------------------------------------------------------
// Phase 1: g_xW[t][k'][n] = x @ Wx + b
// ---------------------------------------------------------------------------
__global__ __launch_bounds__(256) void phase1_wmma(const float* __restrict__ b) {
    extern __shared__ __align__(16) char dsm[];
    __shared__ float rsm[4 * 1024];
    __shared__ float ssm[32 * GP];
    const uint32_t sb = smem_u32(dsm);
    const int tid = threadIdx.x;
    const int w = tid >> 5, lane = tid & 31;
    const int q = w >> 1, p = w & 1;
    const int cta = blockIdx.x;       // k' block (0..127)
    const int t = blockIdx.y;

    // cp.async per-thread mapping
    const int arow = tid >> 3, aseg = tid & 7;
    const uint32_t dA  = (uint32_t)(arow * PE + aseg * 8) * 2;
    const uint32_t dB0 = dA;                                   // rows 0..31
    const uint32_t dB1 = (uint32_t)((arow + 32) * PE + aseg * 8) * 2;
    const char* srcAh = (const char*)(g_WxT_hi + (size_t)(cta * 32 + arow) * DD) + aseg * 16;
    const char* srcAl = (const char*)(g_WxT_lo + (size_t)(cta * 32 + arow) * DD) + aseg * 16;
    const char* srcBh0 = (const char*)(g_xh + ((size_t)arow * TT + t) * DD) + aseg * 16;
    const char* srcBh1 = (const char*)(g_xh + ((size_t)(arow + 32) * TT + t) * DD) + aseg * 16;
    const char* srcBl0 = (const char*)(g_xl + ((size_t)arow * TT + t) * DD) + aseg * 16;
    const char* srcBl1 = (const char*)(g_xl + ((size_t)(arow + 32) * TT + t) * DD) + aseg * 16;

    wmma::fragment<wmma::accumulator, 16, 16, 16, float> acc[2][2];
    #pragma unroll
    for (int mi = 0; mi < 2; mi++)
        #pragma unroll
        for (int ni = 0; ni < 2; ni++) wmma::fill_fragment(acc[mi][ni], 0.0f);

    MAINLOOP_16();

    REDUCE_Q(rsm);
    __syncthreads();
    if (q == 0) {
        #pragma unroll
        for (int mi = 0; mi < 2; mi++)
            #pragma unroll
            for (int ni = 0; ni < 2; ni++)
                wmma::store_matrix_sync(ssm + (mi * 16) * GP + p * 32 + ni * 16,
                                        acc[mi][ni], GP, wmma::mem_row_major);
    }
    __syncthreads();

    float* xwo = g_xW + ((size_t)t * K4 + cta * 32) * 64;
    #pragma unroll
    for (int u = 0; u < 8; u++) {
        const int idx = tid + 256 * u;
        const int lm = idx >> 6, n = idx & 63;
        const int korig = (lm >> 3) * 1024 + cta * 8 + (lm & 7);
        xwo[idx] = ssm[lm * GP + n] + __ldg(&b[korig]);
    }
}

// ---------------------------------------------------------------------------
// Persistent recurrence. 128 CTAs, grid barrier per step.
// ---------------------------------------------------------------------------
__global__ __launch_bounds__(256, 1) void rec_wmma(float* __restrict__ out) {
    extern __shared__ __align__(16) char dsm[];
    __shared__ float rsm[4 * 1024];
    __shared__ float gsm[32 * GP];
    __shared__ float csm[8 * GP];
    const uint32_t sb = smem_u32(dsm);
    const int tid = threadIdx.x;
    const int w = tid >> 5, lane = tid & 31;
    const int q = w >> 1, p = w & 1;
    const int cta = blockIdx.x;

    const int arow = tid >> 3, aseg = tid & 7;
    const uint32_t dA  = (uint32_t)(arow * PE + aseg * 8) * 2;
    const uint32_t dB0 = dA;
    const uint32_t dB1 = (uint32_t)((arow + 32) * PE + aseg * 8) * 2;
    const char* srcAh = (const char*)(g_WhT_hi + (size_t)(cta * 32 + arow) * HH) + aseg * 16;
    const char* srcAl = (const char*)(g_WhT_lo + (size_t)(cta * 32 + arow) * HH) + aseg * 16;
    const size_t bo0 = (size_t)arow * HH;
    const size_t bo1 = (size_t)(arow + 32) * HH;

    for (int i = tid; i < 8 * GP; i += 256) csm[i] = 0.f;
    __syncthreads();

    const int cn = tid >> 2;            // n for combine
    const int jp = (tid & 3) * 2;       // jl pair base

    for (int t = 0; t < TT; t++) {
        const char* srcBh0 = (const char*)(g_hh[t & 1] + bo0) + aseg * 16;
        const char* srcBh1 = (const char*)(g_hh[t & 1] + bo1) + aseg * 16;
        const char* srcBl0 = (const char*)(g_hl[t & 1] + bo0) + aseg * 16;
        const char* srcBl1 = (const char*)(g_hl[t & 1] + bo1) + aseg * 16;

        const float* xwp = g_xW + ((size_t)t * K4 + cta * 32) * 64;
        float xwr[8];
        #pragma unroll
        for (int u = 0; u < 8; u++) xwr[u] = __ldg(&xwp[tid + 256 * u]);

        wmma::fragment<wmma::accumulator, 16, 16, 16, float> acc[2][2];
        #pragma unroll
        for (int mi = 0; mi < 2; mi++)
            #pragma unroll
            for (int ni = 0; ni < 2; ni++) wmma::fill_fragment(acc[mi][ni], 0.0f);

        MAINLOOP_16();

        REDUCE_Q(rsm);
        __syncthreads();
        if (q == 0) {
            #pragma unroll
            for (int mi = 0; mi < 2; mi++)
                #pragma unroll
                for (int ni = 0; ni < 2; ni++)
                    wmma::store_matrix_sync(gsm + (mi * 16) * GP + p * 32 + ni * 16,
                                            acc[mi][ni], GP, wmma::mem_row_major);
        }
        __syncthreads();

        // activation: lm = gate*8 + jl; gate 3 (lm>=24) uses tanh
        #pragma unroll
        for (int u = 0; u < 8; u++) {
            const int idx = tid + 256 * u;
            const int lm = idx >> 6, n = idx & 63;
            const float v = gsm[lm * GP + n] + xwr[u];
            gsm[lm * GP + n] = (lm >= 24) ? tanhf_fast(v) : sigf(v);
        }
        __syncthreads();

        // combine
        float hv[2];
        __nv_bfloat16 hh2[2], hl2[2];
        #pragma unroll
        for (int u = 0; u < 2; u++) {
            const int jl = jp + u;
            const float iv = gsm[(jl)      * GP + cn];
            const float fv = gsm[(8 + jl)  * GP + cn];
            const float ov = gsm[(16 + jl) * GP + cn];
            const float gv = gsm[(24 + jl) * GP + cn];
            const float cprev = csm[jl * GP + cn];
            const float cnew = fv * cprev + iv * gv;
            csm[jl * GP + cn] = cnew;
            const float h = ov * tanhf_fast(cnew);
            hv[u] = h;
            const __nv_bfloat16 hb = __float2bfloat16(h);
            hh2[u] = hb;
            hl2[u] = __float2bfloat16(h - __bfloat162float(hb));
        }
        *(float2*)&out[((size_t)cn * TT + t) * HH + cta * 8 + jp] = make_float2(hv[0], hv[1]);
        const int nb = (t + 1) & 1;
        *(uint32_t*)&g_hh[nb][(size_t)cn * HH + cta * 8 + jp] = *(uint32_t*)hh2;
        *(uint32_t*)&g_hl[nb][(size_t)cn * HH + cta * 8 + jp] = *(uint32_t*)hl2;

        // grid barrier
        __syncthreads();
        if (tid == 0) {
            __threadfence();
            unsigned int ticket = atomicAdd(&g_bar_count, 1);
            if (ticket == NCTA_REC - 1) {
                g_bar_count = 0;
                __threadfence();
                atomicAdd(&g_bar_gen, 1);
            } else {
                while (*(volatile unsigned int*)&g_bar_gen < (unsigned)(t + 1)) { }
            }
            __threadfence();
        }
        __syncthreads();
    }
}

// ---------------------------------------------------------------------------
extern "C" void kernel_launch(void* const* d_in, const int* in_sizes, int n_in,
                              void* d_out, int out_size)
{
    (void)in_sizes; (void)n_in; (void)out_size;
    const float* x  = (const float*)d_in[0];
    const float* h0 = (const float*)d_in[1];
    const float* Wx = (const float*)d_in[2];
    const float* Wh = (const float*)d_in[3];
    const float* b  = (const float*)d_in[4];
    float* out = (float*)d_out;

    // dynamic-smem opt-in (host-side attribute set; no allocation, graph-legal;
    // called every launch — idempotent, no static guards)
    cudaFuncSetAttribute(phase1_wmma, cudaFuncAttributeMaxDynamicSharedMemorySize, DYN_B);
    cudaFuncSetAttribute(rec_wmma,    cudaFuncAttributeMaxDynamicSharedMemorySize, DYN_B);

    xsplit_kernel<<<262144, 256>>>(x);
    wprep_kernel<<<dim3(128, 32), 256>>>(Wx, 0);   // -> g_WxT_hi/lo
    wprep_kernel<<<dim3(128, 32), 256>>>(Wh, 1);   // -> g_WhT_hi/lo
    init_kernel<<<256, 256>>>(h0);
    phase1_wmma<<<dim3(128, 1024), 256, DYN_B>>>(b);
    rec_wmma<<<NCTA_REC, 256, DYN_B>>>(out);
}

// round 14
// speedup vs baseline: 2.3664x; 1.4699x over previous
#include <cuda_runtime.h>
#include <cuda_fp16.h>
#include <mma.h>
#include <math.h>
#include <stdint.h>

using namespace nvcuda;

#define NB 64
#define TT 1024
#define DD 1024
#define HH 1024
#define K4 4096
#define NCTA_REC 128
#define KC 64          // K-chunk (elements)
#define PE 72          // smem pitch fp16 (elements)
#define GP 68          // fp32 staging pitch

// ---------------- device globals ----------------
__device__ float g_xW[(size_t)TT * K4 * NB];          // [t][k'][n]
__device__ __half g_WhT16[(size_t)K4 * HH];           // [k'][j]
__device__ __half g_WxT16[(size_t)K4 * DD];           // [k'][d]
__device__ __half g_x16[(size_t)NB * TT * DD];        // [n][t][d]
__device__ __half g_h16[2][(size_t)NB * HH];          // [buf][n][j]
__device__ unsigned int g_bar_count;
__device__ unsigned int g_bar_gen;

__device__ __forceinline__ float sigf(float v) { return 1.0f / (1.0f + __expf(-v)); }
__device__ __forceinline__ float tanhf_fast(float v) {
    float x = fminf(fmaxf(v, -15.0f), 15.0f);
    float e = __expf(2.0f * x);
    return (e - 1.0f) / (e + 1.0f);
}

// ---------------------------------------------------------------------------
// Preps
// ---------------------------------------------------------------------------
__global__ void xsplit_kernel(const float* __restrict__ x) {
    size_t i = (size_t)blockIdx.x * 256 + threadIdx.x;   // 64M
    g_x16[i] = __float2half(x[i]);
}

// W[j][k] (1024x4096) -> WT16[k'][j], k' = (jout>>3)*32 + gate*8 + (jout&7)
// (destination resolved in device code — host symbol args were the R5-R8 bug)
__global__ void wprep_kernel(const float* __restrict__ W, int which) {
    __half* __restrict__ dst = which ? g_WhT16 : g_WxT16;
    const int k0 = blockIdx.x * 32;
    const int j0 = blockIdx.y * 32;
    __shared__ float tile[32][33];
    const int tid = threadIdx.x;
    const int jj = tid >> 5, kk = tid & 31;
    #pragma unroll
    for (int p = 0; p < 4; p++)
        tile[jj + 8 * p][kk] = W[(size_t)(j0 + jj + 8 * p) * K4 + k0 + kk];
    __syncthreads();
    const int r = tid >> 3, j4 = (tid & 7) * 4;
    const int korig = k0 + r;
    const int gate = korig >> 10, jout = korig & 1023;
    const int kp = (jout >> 3) * 32 + gate * 8 + (jout & 7);
    __half h4[4];
    #pragma unroll
    for (int u = 0; u < 4; u++) h4[u] = __float2half(tile[j4 + u][r]);
    *(uint2*)&dst[(size_t)kp * HH + j0 + j4] = *(uint2*)h4;
}

__global__ void init_kernel(const float* __restrict__ h0) {
    int i = blockIdx.x * 256 + threadIdx.x;   // 65536, [n][j]
    g_h16[0][i] = __float2half(h0[i]);
    if (i == 0) { g_bar_count = 0; g_bar_gen = 0; }
}

// ---------------------------------------------------------------------------
// GEMM core: fp16 single-term. CTA tile 32 k' (m) x 64 n; 8 warps = 4 (ks
// quarter q) x 2 (n-half p); warp tile 32x32 at its q -> 4 frag loads, 4 mma
// per chunk. q-partials reduced via per-lane fragment blobs in smem.
// ---------------------------------------------------------------------------
#define ACCX(j) acc[(j) >> 4][((j) >> 3) & 1].x[(j) & 7]

#define WMMA_CHUNK()                                                             \
    do {                                                                         \
        wmma::fragment<wmma::matrix_a, 16, 16, 16, __half, wmma::row_major> fa[2]; \
        wmma::fragment<wmma::matrix_b, 16, 16, 16, __half, wmma::col_major> fb[2]; \
        _Pragma("unroll")                                                        \
        for (int mi = 0; mi < 2; mi++)                                           \
            wmma::load_matrix_sync(fa[mi], sA + (mi * 16) * PE + q * 16, PE);    \
        _Pragma("unroll")                                                        \
        for (int ni = 0; ni < 2; ni++)                                           \
            wmma::load_matrix_sync(fb[ni], sB + (p * 32 + ni * 16) * PE + q * 16, PE); \
        _Pragma("unroll")                                                        \
        for (int mi = 0; mi < 2; mi++)                                           \
            _Pragma("unroll")                                                    \
            for (int ni = 0; ni < 2; ni++)                                       \
                wmma::mma_sync(acc[mi][ni], fa[mi], fb[ni], acc[mi][ni]);        \
    } while (0)

#define STORE_BLOB(slot_)                                                        \
    do {                                                                         \
        float* bp_ = rsm + (slot_) * 1024 + lane * 4;                            \
        _Pragma("unroll")                                                        \
        for (int e4 = 0; e4 < 8; e4++) {                                         \
            int j_ = e4 * 4;                                                     \
            *(float4*)(bp_ + e4 * 128) =                                         \
                make_float4(ACCX(j_), ACCX(j_ + 1), ACCX(j_ + 2), ACCX(j_ + 3)); \
        }                                                                        \
    } while (0)

#define LOAD_BLOB_ADD(slot_)                                                     \
    do {                                                                         \
        const float* bp_ = rsm + (slot_) * 1024 + lane * 4;                      \
        _Pragma("unroll")                                                        \
        for (int e4 = 0; e4 < 8; e4++) {                                         \
            int j_ = e4 * 4;                                                     \
            float4 v_ = *(const float4*)(bp_ + e4 * 128);                        \
            ACCX(j_) += v_.x; ACCX(j_ + 1) += v_.y;                              \
            ACCX(j_ + 2) += v_.z; ACCX(j_ + 3) += v_.w;                          \
        }                                                                        \
    } while (0)

#define REDUCE_Q()                                                               \
    do {                                                                         \
        __syncthreads();                                                         \
        if (q >= 2) STORE_BLOB((q - 2) * 2 + p);                                 \
        __syncthreads();                                                         \
        if (q < 2) LOAD_BLOB_ADD(q * 2 + p);                                     \
        __syncthreads();                                                         \
        if (q == 1) STORE_BLOB(p);                                               \
        __syncthreads();                                                         \
        if (q == 0) LOAD_BLOB_ADD(p);                                            \
    } while (0)

// Per-chunk loader (R11 pattern): thread -> A slot (arow, aseg) + 2 B rows.
#define MAINLOOP_16()                                                            \
    do {                                                                         \
        uint4 rA, rB0, rB1;                                                      \
        rA  = *(const uint4*)(srcA);                                             \
        rB0 = *(const uint4*)(srcB0);                                            \
        rB1 = *(const uint4*)(srcB1);                                            \
        for (int c = 0; c < 16; c++) {                                           \
            __syncthreads();                                                     \
            *(uint4*)&sA[sAoff] = rA;                                            \
            *(uint4*)&sB[sB0off] = rB0;                                          \
            *(uint4*)&sB[sB1off] = rB1;                                          \
            __syncthreads();                                                     \
            if (c < 15) {                                                        \
                const int o_ = (c + 1) * KC;                                     \
                rA  = *(const uint4*)(srcA + o_);                                \
                rB0 = *(const uint4*)(srcB0 + o_);                               \
                rB1 = *(const uint4*)(srcB1 + o_);                               \
            }                                                                    \
            WMMA_CHUNK();                                                        \
        }                                                                        \
    } while (0)

// ---------------------------------------------------------------------------
// Phase 1: g_xW[t][k'][n] = x @ Wx + b
// ---------------------------------------------------------------------------
__global__ __launch_bounds__(256) void phase1_wmma(const float* __restrict__ b) {
    __shared__ __align__(16) __half sA[32 * PE];
    __shared__ __align__(16) __half sB[64 * PE];
    __shared__ float rsm[4 * 1024];
    __shared__ float ssm[32 * GP];
    const int tid = threadIdx.x;
    const int w = tid >> 5, lane = tid & 31;
    const int q = w >> 1, p = w & 1;
    const int cta = blockIdx.x;       // k' block (0..127)
    const int t = blockIdx.y;

    const int arow = tid >> 3, aseg = tid & 7;
    const int sAoff  = arow * PE + aseg * 8;
    const int sB0off = sAoff;
    const int sB1off = (arow + 32) * PE + aseg * 8;
    const __half* srcA  = g_WxT16 + (size_t)(cta * 32 + arow) * DD + aseg * 8;
    const __half* srcB0 = g_x16 + ((size_t)arow * TT + t) * DD + aseg * 8;
    const __half* srcB1 = g_x16 + ((size_t)(arow + 32) * TT + t) * DD + aseg * 8;

    wmma::fragment<wmma::accumulator, 16, 16, 16, float> acc[2][2];
    #pragma unroll
    for (int mi = 0; mi < 2; mi++)
        #pragma unroll
        for (int ni = 0; ni < 2; ni++) wmma::fill_fragment(acc[mi][ni], 0.0f);

    MAINLOOP_16();

    REDUCE_Q();
    __syncthreads();
    if (q == 0) {
        #pragma unroll
        for (int mi = 0; mi < 2; mi++)
            #pragma unroll
            for (int ni = 0; ni < 2; ni++)
                wmma::store_matrix_sync(ssm + (mi * 16) * GP + p * 32 + ni * 16,
                                        acc[mi][ni], GP, wmma::mem_row_major);
    }
    __syncthreads();

    float* xwo = g_xW + ((size_t)t * K4 + cta * 32) * 64;
    #pragma unroll
    for (int u = 0; u < 8; u++) {
        const int idx = tid + 256 * u;
        const int lm = idx >> 6, n = idx & 63;
        const int korig = (lm >> 3) * 1024 + cta * 8 + (lm & 7);
        xwo[idx] = ssm[lm * GP + n] + __ldg(&b[korig]);
    }
}

// ---------------------------------------------------------------------------
// Persistent recurrence. 128 CTAs, grid barrier per step.
// ---------------------------------------------------------------------------
__global__ __launch_bounds__(256, 1) void rec_wmma(float* __restrict__ out) {
    __shared__ __align__(16) __half sA[32 * PE];
    __shared__ __align__(16) __half sB[64 * PE];
    __shared__ float rsm[4 * 1024];
    __shared__ float gsm[32 * GP];
    __shared__ float csm[8 * GP];
    const int tid = threadIdx.x;
    const int w = tid >> 5, lane = tid & 31;
    const int q = w >> 1, p = w & 1;
    const int cta = blockIdx.x;

    const int arow = tid >> 3, aseg = tid & 7;
    const int sAoff  = arow * PE + aseg * 8;
    const int sB0off = sAoff;
    const int sB1off = (arow + 32) * PE + aseg * 8;
    const __half* srcA = g_WhT16 + (size_t)(cta * 32 + arow) * HH + aseg * 8;
    const size_t bo0 = (size_t)arow * HH + aseg * 8;
    const size_t bo1 = (size_t)(arow + 32) * HH + aseg * 8;

    for (int i = tid; i < 8 * GP; i += 256) csm[i] = 0.f;
    __syncthreads();

    const int cn = tid >> 2;            // n for combine
    const int jp = (tid & 3) * 2;       // jl pair base

    for (int t = 0; t < TT; t++) {
        const __half* srcB0 = g_h16[t & 1] + bo0;
        const __half* srcB1 = g_h16[t & 1] + bo1;

        const float* xwp = g_xW + ((size_t)t * K4 + cta * 32) * 64;
        float xwr[8];
        #pragma unroll
        for (int u = 0; u < 8; u++) xwr[u] = __ldg(&xwp[tid + 256 * u]);

        wmma::fragment<wmma::accumulator, 16, 16, 16, float> acc[2][2];
        #pragma unroll
        for (int mi = 0; mi < 2; mi++)
            #pragma unroll
            for (int ni = 0; ni < 2; ni++) wmma::fill_fragment(acc[mi][ni], 0.0f);

        MAINLOOP_16();

        REDUCE_Q();
        __syncthreads();
        if (q == 0) {
            #pragma unroll
            for (int mi = 0; mi < 2; mi++)
                #pragma unroll
                for (int ni = 0; ni < 2; ni++)
                    wmma::store_matrix_sync(gsm + (mi * 16) * GP + p * 32 + ni * 16,
                                            acc[mi][ni], GP, wmma::mem_row_major);
        }
        __syncthreads();

        // activation: lm = gate*8 + jl; gate 3 (lm>=24) uses tanh
        #pragma unroll
        for (int u = 0; u < 8; u++) {
            const int idx = tid + 256 * u;
            const int lm = idx >> 6, n = idx & 63;
            const float v = gsm[lm * GP + n] + xwr[u];
            gsm[lm * GP + n] = (lm >= 24) ? tanhf_fast(v) : sigf(v);
        }
        __syncthreads();

        // combine: thread -> (n = cn, jl in {jp, jp+1})
        float hv[2];
        __half h2[2];
        #pragma unroll
        for (int u = 0; u < 2; u++) {
            const int jl = jp + u;
            const float iv = gsm[(jl)      * GP + cn];
            const float fv = gsm[(8 + jl)  * GP + cn];
            const float ov = gsm[(16 + jl) * GP + cn];
            const float gv = gsm[(24 + jl) * GP + cn];
            const float cprev = csm[jl * GP + cn];
            const float cnew = fv * cprev + iv * gv;
            csm[jl * GP + cn] = cnew;
            const float h = ov * tanhf_fast(cnew);
            hv[u] = h;
            h2[u] = __float2half(h);
        }
        *(float2*)&out[((size_t)cn * TT + t) * HH + cta * 8 + jp] = make_float2(hv[0], hv[1]);
        const int nb = (t + 1) & 1;
        *(uint32_t*)&g_h16[nb][(size_t)cn * HH + cta * 8 + jp] = *(uint32_t*)h2;

        // grid barrier (128 CTAs, 1/SM, co-resident)
        __syncthreads();
        if (tid == 0) {
            __threadfence();
            unsigned int ticket = atomicAdd(&g_bar_count, 1);
            if (ticket == NCTA_REC - 1) {
                g_bar_count = 0;
                __threadfence();
                atomicAdd(&g_bar_gen, 1);
            } else {
                while (*(volatile unsigned int*)&g_bar_gen < (unsigned)(t + 1)) { }
            }
            __threadfence();
        }
        __syncthreads();
    }
}

// ---------------------------------------------------------------------------
extern "C" void kernel_launch(void* const* d_in, const int* in_sizes, int n_in,
                              void* d_out, int out_size)
{
    (void)in_sizes; (void)n_in; (void)out_size;
    const float* x  = (const float*)d_in[0];
    const float* h0 = (const float*)d_in[1];
    const float* Wx = (const float*)d_in[2];
    const float* Wh = (const float*)d_in[3];
    const float* b  = (const float*)d_in[4];
    float* out = (float*)d_out;

    xsplit_kernel<<<262144, 256>>>(x);
    wprep_kernel<<<dim3(128, 32), 256>>>(Wx, 0);   // -> g_WxT16
    wprep_kernel<<<dim3(128, 32), 256>>>(Wh, 1);   // -> g_WhT16
    init_kernel<<<256, 256>>>(h0);
    phase1_wmma<<<dim3(128, 1024), 256>>>(b);
    rec_wmma<<<NCTA_REC, 256>>>(out);
}

// round 15
// speedup vs baseline: 3.1022x; 1.3109x over previous
#include <cuda_runtime.h>
#include <cuda_fp16.h>
#include <mma.h>
#include <math.h>
#include <stdint.h>

using namespace nvcuda;

#define NB 64
#define TT 1024
#define DD 1024
#define HH 1024
#define K4 4096
#define NCTA_REC 128
#define KC 128                      // K-chunk (elements)
#define PE2 136                     // fp16 smem pitch for 128-wide rows (+8 pad)
#define GP 68                       // fp32 staging pitch
#define SB_OFF (32 * PE2)           // sB element offset inside dynamic tile
#define DYN_B ((32 * PE2 + 64 * PE2) * 2)   // 26112 bytes

// ---------------- device globals ----------------
__device__ float g_xW[(size_t)TT * K4 * NB];          // [t][k'][n]
__device__ __half g_WhT16[(size_t)K4 * HH];           // [k'][j]
__device__ __half g_WxT16[(size_t)K4 * DD];           // [k'][d]
__device__ __half g_x16[(size_t)NB * TT * DD];        // [n][t][d]
__device__ __half g_h16[2][(size_t)NB * HH];          // [buf][n][j]
__device__ unsigned int g_bar_count;
__device__ unsigned int g_bar_gen;

__device__ __forceinline__ float sigf(float v) { return 1.0f / (1.0f + __expf(-v)); }
__device__ __forceinline__ float tanhf_fast(float v) {
    float x = fminf(fmaxf(v, -15.0f), 15.0f);
    float e = __expf(2.0f * x);
    return (e - 1.0f) / (e + 1.0f);
}

// ---------------------------------------------------------------------------
// Preps (validated)
// ---------------------------------------------------------------------------
__global__ void xsplit_kernel(const float* __restrict__ x) {
    size_t i = (size_t)blockIdx.x * 256 + threadIdx.x;   // 64M
    g_x16[i] = __float2half(x[i]);
}

// W[j][k] (1024x4096) -> WT16[k'][j], k' = (jout>>3)*32 + gate*8 + (jout&7)
__global__ void wprep_kernel(const float* __restrict__ W, int which) {
    __half* __restrict__ dst = which ? g_WhT16 : g_WxT16;
    const int k0 = blockIdx.x * 32;
    const int j0 = blockIdx.y * 32;
    __shared__ float tile[32][33];
    const int tid = threadIdx.x;
    const int jj = tid >> 5, kk = tid & 31;
    #pragma unroll
    for (int p = 0; p < 4; p++)
        tile[jj + 8 * p][kk] = W[(size_t)(j0 + jj + 8 * p) * K4 + k0 + kk];
    __syncthreads();
    const int r = tid >> 3, j4 = (tid & 7) * 4;
    const int korig = k0 + r;
    const int gate = korig >> 10, jout = korig & 1023;
    const int kp = (jout >> 3) * 32 + gate * 8 + (jout & 7);
    __half h4[4];
    #pragma unroll
    for (int u = 0; u < 4; u++) h4[u] = __float2half(tile[j4 + u][r]);
    *(uint2*)&dst[(size_t)kp * HH + j0 + j4] = *(uint2*)h4;
}

__global__ void init_kernel(const float* __restrict__ h0) {
    int i = blockIdx.x * 256 + threadIdx.x;   // 65536, [n][j]
    g_h16[0][i] = __float2half(h0[i]);
    if (i == 0) { g_bar_count = 0; g_bar_gen = 0; }
}

// ---------------------------------------------------------------------------
// GEMM core: fp16, KC=128 (8 chunks). CTA tile 32 k' (m) x 64 n; 8 warps =
// 4 (k-quarter q, 32 wide) x 2 (n-half p); warp tile 32x32, 2 ks-steps.
// q-partials: single-bar 6-slot blob reduction.
// ---------------------------------------------------------------------------
#define ACCX(j) acc[(j) >> 4][((j) >> 3) & 1].x[(j) & 7]

#define WMMA_CHUNK()                                                             \
    do {                                                                         \
        _Pragma("unroll")                                                        \
        for (int ks = 0; ks < 2; ks++) {                                         \
            wmma::fragment<wmma::matrix_a, 16, 16, 16, __half, wmma::row_major> fa[2]; \
            wmma::fragment<wmma::matrix_b, 16, 16, 16, __half, wmma::col_major> fb[2]; \
            const int ko_ = q * 32 + ks * 16;                                    \
            _Pragma("unroll")                                                    \
            for (int mi = 0; mi < 2; mi++)                                       \
                wmma::load_matrix_sync(fa[mi], sA + (mi * 16) * PE2 + ko_, PE2); \
            _Pragma("unroll")                                                    \
            for (int ni = 0; ni < 2; ni++)                                       \
                wmma::load_matrix_sync(fb[ni], sB + (p * 32 + ni * 16) * PE2 + ko_, PE2); \
            _Pragma("unroll")                                                    \
            for (int mi = 0; mi < 2; mi++)                                       \
                _Pragma("unroll")                                                \
                for (int ni = 0; ni < 2; ni++)                                   \
                    wmma::mma_sync(acc[mi][ni], fa[mi], fb[ni], acc[mi][ni]);    \
        }                                                                        \
    } while (0)

#define STORE_BLOB(slot_)                                                        \
    do {                                                                         \
        float* bp_ = rsm + (slot_) * 1024 + lane * 4;                            \
        _Pragma("unroll")                                                        \
        for (int e4 = 0; e4 < 8; e4++) {                                         \
            int j_ = e4 * 4;                                                     \
            *(float4*)(bp_ + e4 * 128) =                                         \
                make_float4(ACCX(j_), ACCX(j_ + 1), ACCX(j_ + 2), ACCX(j_ + 3)); \
        }                                                                        \
    } while (0)

#define LOAD_BLOB_ADD(slot_)                                                     \
    do {                                                                         \
        const float* bp_ = rsm + (slot_) * 1024 + lane * 4;                      \
        _Pragma("unroll")                                                        \
        for (int e4 = 0; e4 < 8; e4++) {                                         \
            int j_ = e4 * 4;                                                     \
            float4 v_ = *(const float4*)(bp_ + e4 * 128);                        \
            ACCX(j_) += v_.x; ACCX(j_ + 1) += v_.y;                              \
            ACCX(j_ + 2) += v_.z; ACCX(j_ + 3) += v_.w;                          \
        }                                                                        \
    } while (0)

// one-bar reduction: q=1..3 store to slots (q-1)*2+p; q=0 adds all three
#define REDUCE_Q()                                                               \
    do {                                                                         \
        if (q > 0) STORE_BLOB((q - 1) * 2 + p);                                  \
        __syncthreads();                                                         \
        if (q == 0) { LOAD_BLOB_ADD(p); LOAD_BLOB_ADD(2 + p); LOAD_BLOB_ADD(4 + p); } \
    } while (0)

// loader: A 512 16B-slots (2/thread), B 1024 slots (4/thread); idx>>4 = row,
// idx&15 = 16B segment within the 256B chunk row.
#define MAINLOOP_8()                                                             \
    do {                                                                         \
        uint4 rA[2], rB[4];                                                      \
        _Pragma("unroll")                                                        \
        for (int i_ = 0; i_ < 2; i_++) rA[i_] = *(const uint4*)(srcA[i_]);       \
        _Pragma("unroll")                                                        \
        for (int i_ = 0; i_ < 4; i_++) rB[i_] = *(const uint4*)(srcB[i_]);       \
        for (int c = 0; c < 8; c++) {                                            \
            __syncthreads();                                                     \
            _Pragma("unroll")                                                    \
            for (int i_ = 0; i_ < 2; i_++) *(uint4*)&sA[sAoff[i_]] = rA[i_];     \
            _Pragma("unroll")                                                    \
            for (int i_ = 0; i_ < 4; i_++) *(uint4*)&sB[sBoff[i_]] = rB[i_];     \
            __syncthreads();                                                     \
            if (c < 7) {                                                         \
                const int o_ = (c + 1) * KC;                                     \
                _Pragma("unroll")                                                \
                for (int i_ = 0; i_ < 2; i_++) rA[i_] = *(const uint4*)(srcA[i_] + o_); \
                _Pragma("unroll")                                                \
                for (int i_ = 0; i_ < 4; i_++) rB[i_] = *(const uint4*)(srcB[i_] + o_); \
            }                                                                    \
            WMMA_CHUNK();                                                        \
        }                                                                        \
    } while (0)

// ---------------------------------------------------------------------------
// Phase 1: g_xW[t][k'][n] = x @ Wx + b
// ---------------------------------------------------------------------------
__global__ __launch_bounds__(256) void phase1_wmma(const float* __restrict__ b) {
    extern __shared__ __align__(16) __half dtile[];
    __half* sA = dtile;
    __half* sB = dtile + SB_OFF;
    __shared__ float rsm[6 * 1024];
    __shared__ float ssm[32 * GP];
    const int tid = threadIdx.x;
    const int w = tid >> 5, lane = tid & 31;
    const int q = w >> 1, p = w & 1;
    const int cta = blockIdx.x;       // k' block (0..127)
    const int t = blockIdx.y;

    int sAoff[2], sBoff[4];
    const __half* srcA[2];
    const __half* srcB[4];
    #pragma unroll
    for (int i = 0; i < 2; i++) {
        const int idx = tid + 256 * i, row = idx >> 4, seg = idx & 15;
        sAoff[i] = row * PE2 + seg * 8;
        srcA[i] = g_WxT16 + (size_t)(cta * 32 + row) * DD + seg * 8;
    }
    #pragma unroll
    for (int i = 0; i < 4; i++) {
        const int idx = tid + 256 * i, row = idx >> 4, seg = idx & 15;
        sBoff[i] = row * PE2 + seg * 8;
        srcB[i] = g_x16 + ((size_t)row * TT + t) * DD + seg * 8;
    }

    wmma::fragment<wmma::accumulator, 16, 16, 16, float> acc[2][2];
    #pragma unroll
    for (int mi = 0; mi < 2; mi++)
        #pragma unroll
        for (int ni = 0; ni < 2; ni++) wmma::fill_fragment(acc[mi][ni], 0.0f);

    MAINLOOP_8();

    REDUCE_Q();
    if (q == 0) {
        #pragma unroll
        for (int mi = 0; mi < 2; mi++)
            #pragma unroll
            for (int ni = 0; ni < 2; ni++)
                wmma::store_matrix_sync(ssm + (mi * 16) * GP + p * 32 + ni * 16,
                                        acc[mi][ni], GP, wmma::mem_row_major);
    }
    __syncthreads();

    float* xwo = g_xW + ((size_t)t * K4 + cta * 32) * 64;
    #pragma unroll
    for (int u = 0; u < 8; u++) {
        const int idx = tid + 256 * u;
        const int lm = idx >> 6, n = idx & 63;
        const int korig = (lm >> 3) * 1024 + cta * 8 + (lm & 7);
        xwo[idx] = ssm[lm * GP + n] + __ldg(&b[korig]);
    }
}

// ---------------------------------------------------------------------------
// Persistent recurrence. 128 CTAs, grid barrier per step.
// ---------------------------------------------------------------------------
__global__ __launch_bounds__(256, 1) void rec_wmma(float* __restrict__ out) {
    extern __shared__ __align__(16) __half dtile[];
    __half* sA = dtile;
    __half* sB = dtile + SB_OFF;
    __shared__ float rsm[6 * 1024];
    __shared__ float gsm[32 * GP];
    __shared__ float csm[8 * GP];
    const int tid = threadIdx.x;
    const int w = tid >> 5, lane = tid & 31;
    const int q = w >> 1, p = w & 1;
    const int cta = blockIdx.x;

    int sAoff[2], sBoff[4];
    const __half* srcA[2];
    size_t boff[4];
    #pragma unroll
    for (int i = 0; i < 2; i++) {
        const int idx = tid + 256 * i, row = idx >> 4, seg = idx & 15;
        sAoff[i] = row * PE2 + seg * 8;
        srcA[i] = g_WhT16 + (size_t)(cta * 32 + row) * HH + seg * 8;
    }
    #pragma unroll
    for (int i = 0; i < 4; i++) {
        const int idx = tid + 256 * i, row = idx >> 4, seg = idx & 15;
        sBoff[i] = row * PE2 + seg * 8;
        boff[i] = (size_t)row * HH + seg * 8;
    }

    for (int i = tid; i < 8 * GP; i += 256) csm[i] = 0.f;
    __syncthreads();

    const int cn = tid >> 2;            // n for combine
    const int jp = (tid & 3) * 2;       // jl pair base

    for (int t = 0; t < TT; t++) {
        const __half* srcB[4];
        #pragma unroll
        for (int i = 0; i < 4; i++) srcB[i] = g_h16[t & 1] + boff[i];

        const float* xwp = g_xW + ((size_t)t * K4 + cta * 32) * 64;
        float xwr[8];
        #pragma unroll
        for (int u = 0; u < 8; u++) xwr[u] = __ldg(&xwp[tid + 256 * u]);

        wmma::fragment<wmma::accumulator, 16, 16, 16, float> acc[2][2];
        #pragma unroll
        for (int mi = 0; mi < 2; mi++)
            #pragma unroll
            for (int ni = 0; ni < 2; ni++) wmma::fill_fragment(acc[mi][ni], 0.0f);

        MAINLOOP_8();

        REDUCE_Q();
        if (q == 0) {
            #pragma unroll
            for (int mi = 0; mi < 2; mi++)
                #pragma unroll
                for (int ni = 0; ni < 2; ni++)
                    wmma::store_matrix_sync(gsm + (mi * 16) * GP + p * 32 + ni * 16,
                                            acc[mi][ni], GP, wmma::mem_row_major);
        }
        __syncthreads();

        // activation: lm = gate*8 + jl; gate 3 (lm>=24) uses tanh
        #pragma unroll
        for (int u = 0; u < 8; u++) {
            const int idx = tid + 256 * u;
            const int lm = idx >> 6, n = idx & 63;
            const float v = gsm[lm * GP + n] + xwr[u];
            gsm[lm * GP + n] = (lm >= 24) ? tanhf_fast(v) : sigf(v);
        }
        __syncthreads();

        // combine: thread -> (n = cn, jl in {jp, jp+1})
        float hv[2];
        __half h2[2];
        #pragma unroll
        for (int u = 0; u < 2; u++) {
            const int jl = jp + u;
            const float iv = gsm[(jl)      * GP + cn];
            const float fv = gsm[(8 + jl)  * GP + cn];
            const float ov = gsm[(16 + jl) * GP + cn];
            const float gv = gsm[(24 + jl) * GP + cn];
            const float cprev = csm[jl * GP + cn];
            const float cnew = fv * cprev + iv * gv;
            csm[jl * GP + cn] = cnew;
            const float h = ov * tanhf_fast(cnew);
            hv[u] = h;
            h2[u] = __float2half(h);
        }
        *(float2*)&out[((size_t)cn * TT + t) * HH + cta * 8 + jp] = make_float2(hv[0], hv[1]);
        const int nb = (t + 1) & 1;
        *(uint32_t*)&g_h16[nb][(size_t)cn * HH + cta * 8 + jp] = *(uint32_t*)h2;

        // grid barrier (128 CTAs, 1/SM, co-resident)
        __syncthreads();
        if (tid == 0) {
            __threadfence();
            unsigned int ticket = atomicAdd(&g_bar_count, 1);
            if (ticket == NCTA_REC - 1) {
                g_bar_count = 0;
                __threadfence();
                atomicAdd(&g_bar_gen, 1);
            } else {
                while (*(volatile unsigned int*)&g_bar_gen < (unsigned)(t + 1)) { }
            }
            __threadfence();
        }
        __syncthreads();
    }
}

// ---------------------------------------------------------------------------
extern "C" void kernel_launch(void* const* d_in, const int* in_sizes, int n_in,
                              void* d_out, int out_size)
{
    (void)in_sizes; (void)n_in; (void)out_size;
    const float* x  = (const float*)d_in[0];
    const float* h0 = (const float*)d_in[1];
    const float* Wx = (const float*)d_in[2];
    const float* Wh = (const float*)d_in[3];
    const float* b  = (const float*)d_in[4];
    float* out = (float*)d_out;

    // dynamic-smem opt-in (host attribute set each call; no allocation)
    cudaFuncSetAttribute(phase1_wmma, cudaFuncAttributeMaxDynamicSharedMemorySize, DYN_B);
    cudaFuncSetAttribute(rec_wmma,    cudaFuncAttributeMaxDynamicSharedMemorySize, DYN_B);

    xsplit_kernel<<<262144, 256>>>(x);
    wprep_kernel<<<dim3(128, 32), 256>>>(Wx, 0);   // -> g_WxT16
    wprep_kernel<<<dim3(128, 32), 256>>>(Wh, 1);   // -> g_WhT16
    init_kernel<<<256, 256>>>(h0);
    phase1_wmma<<<dim3(128, 1024), 256, DYN_B>>>(b);
    rec_wmma<<<NCTA_REC, 256, DYN_B>>>(out);
}